// round 14
// baseline (speedup 1.0000x reference)
#include <cuda_runtime.h>
#include <cuda_fp16.h>
#include <cuda_bf16.h>
#include <cstdint>

#define NN 8192
#define FIN 512
#define FF 64
#define SPLIT 5
#define BM 64
#define BJ 32
#define NCH (NN / BJ)        // 256 chunks total
#define ASTR 40              // A_s row stride in fp16 units (ldmatrix-perfect)

typedef unsigned long long ull;

// -------------------- device scratch --------------------
__device__ float g_e1[NN];
__device__ float g_e2[NN];
__device__ unsigned g_ABh[NN];                    // half2 (A', B')
__device__ __align__(16) unsigned short g_Eh[NN]; // E' fp16
__device__ __align__(16) unsigned short g_Fh[NN]; // F' fp16
__device__ float g_blockmax[128];
__device__ unsigned g_Bf[NN * 32];                // frag-major fp16 of Wh^T (1MB)
__device__ uint2 g_WfH[8192];                     // frag-major bf16 hi of W
__device__ uint2 g_WfL[8192];                     // frag-major bf16 lo of W
__device__ float g_num[SPLIT][NN * FF];
__device__ float g_den[SPLIT][NN];

// -------------------- helpers --------------------
__device__ __forceinline__ void cp16(void* sdst, const void* gsrc) {
    unsigned s = (unsigned)__cvta_generic_to_shared(sdst);
    asm volatile("cp.async.cg.shared.global [%0], [%1], 16;\n" :: "r"(s), "l"(gsrc));
}
#define CP_COMMIT() asm volatile("cp.async.commit_group;\n" ::: "memory")
#define CP_WAIT0()  asm volatile("cp.async.wait_group 0;\n" ::: "memory")

__device__ __forceinline__ void mma_f16(float* d, unsigned a0, unsigned a1,
                                        unsigned a2, unsigned a3,
                                        unsigned b0, unsigned b1) {
    asm("mma.sync.aligned.m16n8k16.row.col.f32.f16.f16.f32 "
        "{%0,%1,%2,%3}, {%4,%5,%6,%7}, {%8,%9}, {%0,%1,%2,%3};"
        : "+f"(d[0]), "+f"(d[1]), "+f"(d[2]), "+f"(d[3])
        : "r"(a0), "r"(a1), "r"(a2), "r"(a3), "r"(b0), "r"(b1));
}
__device__ __forceinline__ void mma_bf16(float* d, unsigned a0, unsigned a1,
                                         unsigned a2, unsigned a3,
                                         unsigned b0, unsigned b1) {
    asm("mma.sync.aligned.m16n8k16.row.col.f32.bf16.bf16.f32 "
        "{%0,%1,%2,%3}, {%4,%5,%6,%7}, {%8,%9}, {%0,%1,%2,%3};"
        : "+f"(d[0]), "+f"(d[1]), "+f"(d[2]), "+f"(d[3])
        : "r"(a0), "r"(a1), "r"(a2), "r"(a3), "r"(b0), "r"(b1));
}

__device__ __forceinline__ void bfsplit2(float x0, float x1, unsigned& hi, unsigned& lo) {
    __nv_bfloat16 h0 = __float2bfloat16_rn(x0);
    __nv_bfloat16 h1 = __float2bfloat16_rn(x1);
    __nv_bfloat16 l0 = __float2bfloat16_rn(x0 - __bfloat162float(h0));
    __nv_bfloat16 l1 = __float2bfloat16_rn(x1 - __bfloat162float(h1));
    __nv_bfloat162 hp = __halves2bfloat162(h0, h1);
    __nv_bfloat162 lp = __halves2bfloat162(l0, l1);
    hi = *(unsigned*)&hp;
    lo = *(unsigned*)&lp;
}

// -------------------- K0w: W -> frag-major bf16 hi/lo --------------------
__global__ __launch_bounds__(256) void k0w(const float* __restrict__ W) {
    int f = blockIdx.x * 256 + threadIdx.x;   // 0..8191
    int lane = f & 31;
    int kb = (f >> 8) * 16 + (lane & 3) * 2;  // k base (pair start)
    int n = (((f >> 5) & 7) << 3) + (lane >> 2);
    float x0 = W[kb * FF + n];
    float x1 = W[(kb + 1) * FF + n];
    float x2 = W[(kb + 8) * FF + n];
    float x3 = W[(kb + 9) * FF + n];
    uint2 hi, lo;
    bfsplit2(x0, x1, hi.x, lo.x);
    bfsplit2(x2, x3, hi.y, lo.y);
    g_WfH[f] = hi;
    g_WfL[f] = lo;
}

// -------------------- K1: Wh = h @ W (3-pass bf16 mma), fused epilogue --------------------
__global__ __launch_bounds__(256) void k1_gemm(const float* __restrict__ h,
                                               const float* __restrict__ W,
                                               const float* __restrict__ a) {
    __shared__ __align__(16) float smemU[64 * 68];   // mainloop A tiles / epilogue WhS
    __shared__ float red[64];
    unsigned short* AhH = (unsigned short*)smemU;            // 64*40 hw = 5120 B
    unsigned short* AhL = (unsigned short*)smemU + 64 * ASTR;
    int t = threadIdx.x;
    int lane = t & 31;
    int w = t >> 5;                // 0..7
    int r0 = blockIdx.x * 64;
    int row = t >> 2;              // 0..63 (staging row)
    int seg = t & 3;               // 8-col segment
    int mrow = (w & 3) * 16;       // warp m-tile rows
    int ng = w >> 2;               // warp n-group: n-tiles ng*4..+3

    unsigned sb_hi = (unsigned)__cvta_generic_to_shared(AhH);
    unsigned sb_lo = (unsigned)__cvta_generic_to_shared(AhL);
    unsigned a_off = (unsigned)((((lane & 7) + ((lane >> 3) & 1) * 8) * ASTR +
                                 (lane >> 4) * 8) * 2) + (unsigned)(mrow * ASTR * 2);

    float acc[4][4];
#pragma unroll
    for (int ft = 0; ft < 4; ft++)
#pragma unroll
        for (int u = 0; u < 4; u++) acc[ft][u] = 0.f;

    for (int it = 0; it < 16; it++) {
        int k0 = it * 32;
        const float* hp = &h[(size_t)(r0 + row) * FIN + k0 + seg * 8];
        float4 v0 = *(const float4*)hp;
        float4 v1 = *(const float4*)(hp + 4);
        uint4 hiw, low;
        bfsplit2(v0.x, v0.y, hiw.x, low.x);
        bfsplit2(v0.z, v0.w, hiw.y, low.y);
        bfsplit2(v1.x, v1.y, hiw.z, low.z);
        bfsplit2(v1.z, v1.w, hiw.w, low.w);
        __syncthreads();   // prev iter's ldmatrix reads complete
        *(uint4*)&AhH[row * ASTR + seg * 8] = hiw;
        *(uint4*)&AhL[row * ASTR + seg * 8] = low;
        __syncthreads();   // tiles visible
#pragma unroll
        for (int kt = 0; kt < 2; kt++) {
            unsigned addr_h = sb_hi + a_off + (unsigned)(kt * 32);
            unsigned addr_l = sb_lo + a_off + (unsigned)(kt * 32);
            unsigned ah0, ah1, ah2, ah3, al0, al1, al2, al3;
            asm("ldmatrix.sync.aligned.m8n8.x4.shared.b16 {%0,%1,%2,%3}, [%4];"
                : "=r"(ah0), "=r"(ah1), "=r"(ah2), "=r"(ah3) : "r"(addr_h));
            asm("ldmatrix.sync.aligned.m8n8.x4.shared.b16 {%0,%1,%2,%3}, [%4];"
                : "=r"(al0), "=r"(al1), "=r"(al2), "=r"(al3) : "r"(addr_l));
            int ktg = it * 2 + kt;
#pragma unroll
            for (int ft = 0; ft < 4; ft++) {
                uint2 bh = g_WfH[(ktg * 8 + ng * 4 + ft) * 32 + lane];
                uint2 bl = g_WfL[(ktg * 8 + ng * 4 + ft) * 32 + lane];
                mma_bf16(acc[ft], ah0, ah1, ah2, ah3, bh.x, bh.y);
                mma_bf16(acc[ft], al0, al1, al2, al3, bh.x, bh.y);
                mma_bf16(acc[ft], ah0, ah1, ah2, ah3, bl.x, bl.y);
            }
        }
    }

    // ---- write acc to WhS (fp32, stride 68), then original epilogue ----
    __syncthreads();
    float* WhS = smemU;
#pragma unroll
    for (int ft = 0; ft < 4; ft++) {
        int col = ng * 32 + ft * 8 + (lane & 3) * 2;
        int rr = mrow + (lane >> 2);
        *(float2*)&WhS[rr * 68 + col] = make_float2(acc[ft][0], acc[ft][1]);
        *(float2*)&WhS[(rr + 8) * 68 + col] = make_float2(acc[ft][2], acc[ft][3]);
    }
    __syncthreads();
    if (t < 64) {
        const float4* wr = (const float4*)&WhS[t * 68];
        float e1 = 0.f, e2 = 0.f;
#pragma unroll
        for (int q = 0; q < 16; q++) {
            float4 v = wr[q];
            float4 a1 = *(const float4*)&a[q * 4];
            float4 a2 = *(const float4*)&a[FF + q * 4];
            e1 += v.x * a1.x + v.y * a1.y + v.z * a1.z + v.w * a1.w;
            e2 += v.x * a2.x + v.y * a2.y + v.z * a2.z + v.w * a2.w;
        }
        g_e1[r0 + t] = e1;
        g_e2[r0 + t] = e2;
        red[t] = e2;
    }
    __syncthreads();
    if (t < 32) {
        float m = fmaxf(red[t], red[t + 32]);
#pragma unroll
        for (int o = 16; o > 0; o >>= 1)
            m = fmaxf(m, __shfl_xor_sync(0xffffffffu, m, o));
        if (t == 0) g_blockmax[blockIdx.x] = m;
    }
    // fp16 frag-major conversion of this block's 64 Wh rows (j side)
    {
        int il = t >> 2, fq = t & 3;
        int j = r0 + il;
        int cch = j >> 5, kk = j & 31;
        int kt2 = kk >> 4, k2v = kk & 15;
        int rg = k2v >> 3, hf = k2v & 1, lq = (k2v & 7) >> 1;
        unsigned base = (unsigned)cch * 1024u;
        unsigned short* bp = (unsigned short*)g_Bf;
#pragma unroll
        for (int u = 0; u < 16; u++) {
            int f = fq * 16 + u;
            int ft = f >> 3, n = f & 7;
            unsigned idx32 = base + (unsigned)(((kt2 * 8 + ft) * 32 + n * 4 + lq) * 2 + rg);
            __half hv = __float2half_rn(WhS[il * 68 + f]);
            bp[idx32 * 2 + hf] = *(unsigned short*)&hv;
        }
    }
}

// -------------------- K3: global max (tree reduce), A'B'/E'/F' --------------------
__global__ __launch_bounds__(256) void k3_ef() {
    __shared__ float mred[128];
    __shared__ float mbc;
    int t = threadIdx.x;
    int i = blockIdx.x * 256 + t;
    if (t < 128) mred[t] = g_blockmax[t];
    __syncthreads();
    if (t < 32) {
        float m = fmaxf(fmaxf(mred[t], mred[t + 32]), fmaxf(mred[t + 64], mred[t + 96]));
#pragma unroll
        for (int o = 16; o > 0; o >>= 1)
            m = fmaxf(m, __shfl_xor_sync(0xffffffffu, m, o));
        if (t == 0) mbc = m;
    }
    __syncthreads();
    float m = mbc;
    float e1 = g_e1[i], e2 = g_e2[i];
    float x = e1 + m;
    float C = (x > 0.f) ? x : 0.2f * x;          // lrelu(e1 + M)
    float Ap = expf(x - C);
    float Bp = expf(0.2f * x - C);
    float Ep = expf(e2 - m);
    float Fp = expf(0.2f * (e2 - m));
    __half2 ab = __floats2half2_rn(Ap, Bp);
    g_ABh[i] = *(unsigned*)&ab;
    __half eh = __float2half_rn(Ep), fh = __float2half_rn(Fp);
    g_Eh[i] = *(unsigned short*)&eh;
    g_Fh[i] = *(unsigned short*)&fh;
}

// -------------------- K4: fused adj + fp16 mma attention GEMM (R13, unchanged) --------------------
__global__ __launch_bounds__(128, 5) void k4_main(const int* __restrict__ adj) {
    __shared__ unsigned short Ah_s[2][BM * ASTR];     // 2 x 5120 B
    __shared__ __align__(16) unsigned Bf_s[2][1024];  // 8192 B

    int t = threadIdx.x;
    int lane = t & 31;
    int wid = t >> 5;                 // 0..3
    int bi = blockIdx.x & 127;
    int bs = blockIdx.x >> 7;         // 0..4
    int r0 = bi * BM;
    int cstart = bs * 51 + (bs > 0 ? 1 : 0);
    int cend = cstart + 51 + (bs == 0 ? 1 : 0);

    int mw = wid & 1;                 // mma rows mw*32..+31
    int nw = wid >> 1;                // mma cols nw*32..+31

    // gen mapping: lane -> (row sub, j block of 4)
    int rql = lane >> 3;              // 0..3
    int jb = lane & 7;                // j = 4*jb .. 4*jb+3

    __half2 aa[4], bb[4];
    const uint4* adjp[4];
#pragma unroll
    for (int q = 0; q < 4; q++) {
        int rl = wid * 16 + 4 * q + rql;
        unsigned abu = g_ABh[r0 + rl];
        __half2 abh = *(__half2*)&abu;
        aa[q] = __half2half2(__low2half(abh));
        bb[q] = __half2half2(__high2half(abh));
        adjp[q] = (const uint4*)(adj + (size_t)(r0 + rl) * NN + 4 * jb);
    }
    const uint2* epE = (const uint2*)g_Eh;
    const uint2* epF = (const uint2*)g_Fh;

    unsigned a_smem = (unsigned)__cvta_generic_to_shared(&Ah_s[0][0]);
    unsigned a_lane = a_smem +
        (unsigned)((((lane & 7) + ((lane >> 3) & 1) * 8) * ASTR + (lane >> 4) * 8) * 2);

    cp16(&Bf_s[cstart & 1][t * 8], &g_Bf[cstart * 1024 + t * 8]);
    cp16(&Bf_s[cstart & 1][t * 8 + 4], &g_Bf[cstart * 1024 + t * 8 + 4]);
    CP_COMMIT();

    uint4 av[4];
    uint2 eu, fu;
#pragma unroll
    for (int q = 0; q < 4; q++) av[q] = adjp[q][(size_t)cstart * 8];
    eu = epE[cstart * 8 + jb];
    fu = epF[cstart * 8 + jb];

    float acc[2][4][4];
#pragma unroll
    for (int mt = 0; mt < 2; mt++)
#pragma unroll
        for (int ft = 0; ft < 4; ft++)
#pragma unroll
            for (int u = 0; u < 4; u++) acc[mt][ft][u] = 0.f;
    float dnf[4] = {0.f, 0.f, 0.f, 0.f};

    for (int c = cstart; c < cend; c++) {
        int cur = c & 1;

        __half2 e01 = *(__half2*)&eu.x;
        __half2 e23 = *(__half2*)&eu.y;
        __half2 f01 = *(__half2*)&fu.x;
        __half2 f23 = *(__half2*)&fu.y;
#pragma unroll
        for (int q = 0; q < 4; q++) {
            uint4 a4 = av[q];
            __half2 w0 = __hmax2(__hmul2(aa[q], e01), __hmul2(bb[q], f01));
            unsigned m0 = a4.x * 0x3C00u + a4.y * 0x3C000000u;
            w0 = __hmul2(w0, *(__half2*)&m0);
            __half2 w1 = __hmax2(__hmul2(aa[q], e23), __hmul2(bb[q], f23));
            unsigned m1 = a4.z * 0x3C00u + a4.w * 0x3C000000u;
            w1 = __hmul2(w1, *(__half2*)&m1);
            __half2 dn2 = __hadd2(w0, w1);
            float2 df = __half22float2(dn2);
            dnf[q] += df.x + df.y;
            int rl = wid * 16 + 4 * q + rql;
            *(uint2*)&Ah_s[cur][rl * ASTR + 4 * jb] =
                make_uint2(*(unsigned*)&w0, *(unsigned*)&w1);
        }

        if (c + 1 < cend) {
#pragma unroll
            for (int q = 0; q < 4; q++) av[q] = adjp[q][(size_t)(c + 1) * 8];
            eu = epE[(c + 1) * 8 + jb];
            fu = epF[(c + 1) * 8 + jb];
        }

        CP_WAIT0();
        __syncthreads();

        if (c + 1 < cend) {
            cp16(&Bf_s[cur ^ 1][t * 8], &g_Bf[(c + 1) * 1024 + t * 8]);
            cp16(&Bf_s[cur ^ 1][t * 8 + 4], &g_Bf[(c + 1) * 1024 + t * 8 + 4]);
            CP_COMMIT();
        }

#pragma unroll
        for (int kt = 0; kt < 2; kt++) {
            uint2 bfr[4];
#pragma unroll
            for (int ft = 0; ft < 4; ft++) {
                int ftg = nw * 4 + ft;
                bfr[ft] = *(const uint2*)&Bf_s[cur][((kt * 8 + ftg) * 32 + lane) * 2];
            }
#pragma unroll
            for (int mt = 0; mt < 2; mt++) {
                unsigned addr = a_lane + (unsigned)(cur * (BM * ASTR * 2)) +
                    (unsigned)(((mw * 32 + mt * 16) * ASTR + kt * 16) * 2);
                unsigned a0, a1, a2, a3;
                asm("ldmatrix.sync.aligned.m8n8.x4.shared.b16 {%0,%1,%2,%3}, [%4];"
                    : "=r"(a0), "=r"(a1), "=r"(a2), "=r"(a3) : "r"(addr));
#pragma unroll
                for (int ft = 0; ft < 4; ft++)
                    mma_f16(acc[mt][ft], a0, a1, a2, a3, bfr[ft].x, bfr[ft].y);
            }
        }
    }

#pragma unroll
    for (int mt = 0; mt < 2; mt++) {
        int r1 = r0 + mw * 32 + mt * 16 + (lane >> 2);
#pragma unroll
        for (int ft = 0; ft < 4; ft++) {
            int col = nw * 32 + ft * 8 + (lane & 3) * 2;
            *(float2*)&g_num[bs][r1 * FF + col] = make_float2(acc[mt][ft][0], acc[mt][ft][1]);
            *(float2*)&g_num[bs][(r1 + 8) * FF + col] = make_float2(acc[mt][ft][2], acc[mt][ft][3]);
        }
    }
#pragma unroll
    for (int q = 0; q < 4; q++) {
        float v = dnf[q];
        v += __shfl_xor_sync(0xffffffffu, v, 1);
        v += __shfl_xor_sync(0xffffffffu, v, 2);
        v += __shfl_xor_sync(0xffffffffu, v, 4);
        if (jb == 0) g_den[bs][r0 + wid * 16 + 4 * q + rql] = v;
    }
}

// -------------------- K5: reduce splits, normalize, ELU --------------------
__global__ __launch_bounds__(256) void k5_out(float* __restrict__ out) {
    int idx4 = blockIdx.x * 256 + threadIdx.x;
    int idx = idx4 * 4;
    int i = idx >> 6;
    float4 num = make_float4(0.f, 0.f, 0.f, 0.f);
    float den = 0.f;
#pragma unroll
    for (int s = 0; s < SPLIT; s++) {
        float4 v = *(const float4*)&g_num[s][idx];
        num.x += v.x; num.y += v.y; num.z += v.z; num.w += v.w;
        den += g_den[s][i];
    }
    den = fmaxf(den, 1e-30f);
    float r = 1.f / den;
    float4 o;
    o.x = num.x * r; o.y = num.y * r; o.z = num.z * r; o.w = num.w * r;
    o.x = (o.x > 0.f) ? o.x : expm1f(o.x);
    o.y = (o.y > 0.f) ? o.y : expm1f(o.y);
    o.z = (o.z > 0.f) ? o.z : expm1f(o.z);
    o.w = (o.w > 0.f) ? o.w : expm1f(o.w);
    *(float4*)&out[idx] = o;
}

// -------------------- launch --------------------
extern "C" void kernel_launch(void* const* d_in, const int* in_sizes, int n_in,
                              void* d_out, int out_size) {
    const float* h = (const float*)d_in[0];
    const int* adj = (const int*)d_in[1];
    const float* W = (const float*)d_in[2];
    const float* a = (const float*)d_in[3];
    float* out = (float*)d_out;

    k0w<<<32, 256>>>(W);
    k1_gemm<<<NN / 64, 256>>>(h, W, a);
    k3_ef<<<NN / 256, 256>>>();
    k4_main<<<128 * SPLIT, 128>>>(adj);
    k5_out<<<(NN * FF) / 1024, 256>>>(out);
}

// round 16
// speedup vs baseline: 1.5723x; 1.5723x over previous
#include <cuda_runtime.h>
#include <cuda_fp16.h>
#include <cstdint>

#define NN 8192
#define FIN 512
#define FF 64
#define SPLIT 5
#define BM 64
#define BJ 32
#define NCH (NN / BJ)        // 256 chunks total
#define ASTR 40              // A_s row stride in fp16 units (ldmatrix-perfect)

typedef unsigned long long ull;

// -------------------- device scratch --------------------
__device__ float g_e1[NN];
__device__ float g_e2[NN];
__device__ unsigned g_ABh[NN];                    // half2 (A', B')
__device__ __align__(16) unsigned short g_Eh[NN]; // E' fp16
__device__ __align__(16) unsigned short g_Fh[NN]; // F' fp16
__device__ float g_blockmax[128];
__device__ unsigned g_Bf[NN * 32];                // frag-major fp16 of Wh^T (1MB)
__device__ uint2 g_Wf[8192];                      // frag-major fp16 of W (64KB)
__device__ float g_num[SPLIT][NN * FF];
__device__ float g_den[SPLIT][NN];

// -------------------- helpers --------------------
__device__ __forceinline__ void cp16(void* sdst, const void* gsrc) {
    unsigned s = (unsigned)__cvta_generic_to_shared(sdst);
    asm volatile("cp.async.cg.shared.global [%0], [%1], 16;\n" :: "r"(s), "l"(gsrc));
}
#define CP_COMMIT() asm volatile("cp.async.commit_group;\n" ::: "memory")
#define CP_WAIT0()  asm volatile("cp.async.wait_group 0;\n" ::: "memory")

__device__ __forceinline__ void mma_f16(float* d, unsigned a0, unsigned a1,
                                        unsigned a2, unsigned a3,
                                        unsigned b0, unsigned b1) {
    asm("mma.sync.aligned.m16n8k16.row.col.f32.f16.f16.f32 "
        "{%0,%1,%2,%3}, {%4,%5,%6,%7}, {%8,%9}, {%0,%1,%2,%3};"
        : "+f"(d[0]), "+f"(d[1]), "+f"(d[2]), "+f"(d[3])
        : "r"(a0), "r"(a1), "r"(a2), "r"(a3), "r"(b0), "r"(b1));
}

// -------------------- K0w: W -> frag-major fp16 --------------------
__global__ __launch_bounds__(256) void k0w(const float* __restrict__ W) {
    int f = blockIdx.x * 256 + threadIdx.x;   // 0..8191
    int lane = f & 31;
    int kb = (f >> 8) * 16 + (lane & 3) * 2;  // k base (pair start)
    int n = (((f >> 5) & 7) << 3) + (lane >> 2);
    __half2 p0 = __floats2half2_rn(W[kb * FF + n], W[(kb + 1) * FF + n]);
    __half2 p1 = __floats2half2_rn(W[(kb + 8) * FF + n], W[(kb + 9) * FF + n]);
    g_Wf[f] = make_uint2(*(unsigned*)&p0, *(unsigned*)&p1);
}

// -------------------- K1: Wh = h @ W (fp16 mma), fused epilogue --------------------
__global__ __launch_bounds__(256) void k1_gemm(const float* __restrict__ h,
                                               const float* __restrict__ a) {
    __shared__ __align__(16) float smemU[64 * 68];   // A tile (fp16) / epilogue WhS
    __shared__ float red[64];
    unsigned short* Ah = (unsigned short*)smemU;     // 64*40 hw = 5120 B
    int t = threadIdx.x;
    int lane = t & 31;
    int w = t >> 5;                // 0..7
    int r0 = blockIdx.x * 64;
    int row = t >> 2;              // staging row 0..63
    int seg = t & 3;               // 8-col segment
    int mrow = (w & 3) * 16;       // warp m-tile rows
    int ng = w >> 2;               // warp n-group: n-tiles ng*4..+3

    unsigned sb = (unsigned)__cvta_generic_to_shared(Ah);
    unsigned a_off = (unsigned)((((lane & 7) + ((lane >> 3) & 1) * 8) * ASTR +
                                 (lane >> 4) * 8) * 2) + (unsigned)(mrow * ASTR * 2);

    const float* hp0 = &h[(size_t)(r0 + row) * FIN + seg * 8];
    float4 v0 = *(const float4*)hp0;
    float4 v1 = *(const float4*)(hp0 + 4);

    float acc[4][4];
#pragma unroll
    for (int ft = 0; ft < 4; ft++)
#pragma unroll
        for (int u = 0; u < 4; u++) acc[ft][u] = 0.f;

    for (int it = 0; it < 16; it++) {
        // B frag prefetch for this iter (L2; covered by barriers+STS below)
        uint2 bf[2][4];
#pragma unroll
        for (int kt = 0; kt < 2; kt++)
#pragma unroll
            for (int ft = 0; ft < 4; ft++)
                bf[kt][ft] = g_Wf[((it * 2 + kt) * 8 + ng * 4 + ft) * 32 + lane];

        __syncthreads();   // prev iter's ldmatrix reads complete
        __half2 p0 = __floats2half2_rn(v0.x, v0.y);
        __half2 p1 = __floats2half2_rn(v0.z, v0.w);
        __half2 p2 = __floats2half2_rn(v1.x, v1.y);
        __half2 p3 = __floats2half2_rn(v1.z, v1.w);
        *(uint4*)&Ah[row * ASTR + seg * 8] =
            make_uint4(*(unsigned*)&p0, *(unsigned*)&p1,
                       *(unsigned*)&p2, *(unsigned*)&p3);
        __syncthreads();   // tile visible

        // h register prefetch for next iter (hidden under mma)
        if (it + 1 < 16) {
            v0 = *(const float4*)(hp0 + (it + 1) * 32);
            v1 = *(const float4*)(hp0 + (it + 1) * 32 + 4);
        }

#pragma unroll
        for (int kt = 0; kt < 2; kt++) {
            unsigned addr = sb + a_off + (unsigned)(kt * 32);
            unsigned a0, a1, a2, a3;
            // volatile + memory clobber: pin against barrier, forbid cross-iter CSE
            asm volatile(
                "ldmatrix.sync.aligned.m8n8.x4.shared.b16 {%0,%1,%2,%3}, [%4];"
                : "=r"(a0), "=r"(a1), "=r"(a2), "=r"(a3) : "r"(addr) : "memory");
#pragma unroll
            for (int ft = 0; ft < 4; ft++)
                mma_f16(acc[ft], a0, a1, a2, a3, bf[kt][ft].x, bf[kt][ft].y);
        }
    }

    // ---- write acc to WhS (fp32, stride 68), then original epilogue ----
    __syncthreads();
    float* WhS = smemU;
#pragma unroll
    for (int ft = 0; ft < 4; ft++) {
        int col = ng * 32 + ft * 8 + (lane & 3) * 2;
        int rr = mrow + (lane >> 2);
        *(float2*)&WhS[rr * 68 + col] = make_float2(acc[ft][0], acc[ft][1]);
        *(float2*)&WhS[(rr + 8) * 68 + col] = make_float2(acc[ft][2], acc[ft][3]);
    }
    __syncthreads();
    if (t < 64) {
        const float4* wr = (const float4*)&WhS[t * 68];
        float e1 = 0.f, e2 = 0.f;
#pragma unroll
        for (int q = 0; q < 16; q++) {
            float4 v = wr[q];
            float4 a1 = *(const float4*)&a[q * 4];
            float4 a2 = *(const float4*)&a[FF + q * 4];
            e1 += v.x * a1.x + v.y * a1.y + v.z * a1.z + v.w * a1.w;
            e2 += v.x * a2.x + v.y * a2.y + v.z * a2.z + v.w * a2.w;
        }
        g_e1[r0 + t] = e1;
        g_e2[r0 + t] = e2;
        red[t] = e2;
    }
    __syncthreads();
    if (t < 32) {
        float m = fmaxf(red[t], red[t + 32]);
#pragma unroll
        for (int o = 16; o > 0; o >>= 1)
            m = fmaxf(m, __shfl_xor_sync(0xffffffffu, m, o));
        if (t == 0) g_blockmax[blockIdx.x] = m;
    }
    // fp16 frag-major conversion of this block's 64 Wh rows (j side)
    {
        int il = t >> 2, fq = t & 3;
        int j = r0 + il;
        int cch = j >> 5, kk = j & 31;
        int kt2 = kk >> 4, k2v = kk & 15;
        int rg = k2v >> 3, hf = k2v & 1, lq = (k2v & 7) >> 1;
        unsigned base = (unsigned)cch * 1024u;
        unsigned short* bp = (unsigned short*)g_Bf;
#pragma unroll
        for (int u = 0; u < 16; u++) {
            int f = fq * 16 + u;
            int ft = f >> 3, n = f & 7;
            unsigned idx32 = base + (unsigned)(((kt2 * 8 + ft) * 32 + n * 4 + lq) * 2 + rg);
            __half hv = __float2half_rn(WhS[il * 68 + f]);
            bp[idx32 * 2 + hf] = *(unsigned short*)&hv;
        }
    }
}

// -------------------- K3: global max (tree reduce), A'B'/E'/F' --------------------
__global__ __launch_bounds__(256) void k3_ef() {
    __shared__ float mred[128];
    __shared__ float mbc;
    int t = threadIdx.x;
    int i = blockIdx.x * 256 + t;
    if (t < 128) mred[t] = g_blockmax[t];
    __syncthreads();
    if (t < 32) {
        float m = fmaxf(fmaxf(mred[t], mred[t + 32]), fmaxf(mred[t + 64], mred[t + 96]));
#pragma unroll
        for (int o = 16; o > 0; o >>= 1)
            m = fmaxf(m, __shfl_xor_sync(0xffffffffu, m, o));
        if (t == 0) mbc = m;
    }
    __syncthreads();
    float m = mbc;
    float e1 = g_e1[i], e2 = g_e2[i];
    float x = e1 + m;
    float C = (x > 0.f) ? x : 0.2f * x;          // lrelu(e1 + M)
    float Ap = expf(x - C);
    float Bp = expf(0.2f * x - C);
    float Ep = expf(e2 - m);
    float Fp = expf(0.2f * (e2 - m));
    __half2 ab = __floats2half2_rn(Ap, Bp);
    g_ABh[i] = *(unsigned*)&ab;
    __half eh = __float2half_rn(Ep), fh = __float2half_rn(Fp);
    g_Eh[i] = *(unsigned short*)&eh;
    g_Fh[i] = *(unsigned short*)&fh;
}

// -------------------- K4: fused adj + fp16 mma attention GEMM (unchanged, 59.4us) --------------------
__global__ __launch_bounds__(128, 5) void k4_main(const int* __restrict__ adj) {
    __shared__ unsigned short Ah_s[2][BM * ASTR];     // 2 x 5120 B
    __shared__ __align__(16) unsigned Bf_s[2][1024];  // 8192 B

    int t = threadIdx.x;
    int lane = t & 31;
    int wid = t >> 5;                 // 0..3
    int bi = blockIdx.x & 127;
    int bs = blockIdx.x >> 7;         // 0..4
    int r0 = bi * BM;
    int cstart = bs * 51 + (bs > 0 ? 1 : 0);
    int cend = cstart + 51 + (bs == 0 ? 1 : 0);

    int mw = wid & 1;                 // mma rows mw*32..+31
    int nw = wid >> 1;                // mma cols nw*32..+31

    int rql = lane >> 3;              // 0..3
    int jb = lane & 7;                // j = 4*jb .. 4*jb+3

    __half2 aa[4], bb[4];
    const uint4* adjp[4];
#pragma unroll
    for (int q = 0; q < 4; q++) {
        int rl = wid * 16 + 4 * q + rql;
        unsigned abu = g_ABh[r0 + rl];
        __half2 abh = *(__half2*)&abu;
        aa[q] = __half2half2(__low2half(abh));
        bb[q] = __half2half2(__high2half(abh));
        adjp[q] = (const uint4*)(adj + (size_t)(r0 + rl) * NN + 4 * jb);
    }
    const uint2* epE = (const uint2*)g_Eh;
    const uint2* epF = (const uint2*)g_Fh;

    unsigned a_smem = (unsigned)__cvta_generic_to_shared(&Ah_s[0][0]);
    unsigned a_lane = a_smem +
        (unsigned)((((lane & 7) + ((lane >> 3) & 1) * 8) * ASTR + (lane >> 4) * 8) * 2);

    cp16(&Bf_s[cstart & 1][t * 8], &g_Bf[cstart * 1024 + t * 8]);
    cp16(&Bf_s[cstart & 1][t * 8 + 4], &g_Bf[cstart * 1024 + t * 8 + 4]);
    CP_COMMIT();

    uint4 av[4];
    uint2 eu, fu;
#pragma unroll
    for (int q = 0; q < 4; q++) av[q] = adjp[q][(size_t)cstart * 8];
    eu = epE[cstart * 8 + jb];
    fu = epF[cstart * 8 + jb];

    float acc[2][4][4];
#pragma unroll
    for (int mt = 0; mt < 2; mt++)
#pragma unroll
        for (int ft = 0; ft < 4; ft++)
#pragma unroll
            for (int u = 0; u < 4; u++) acc[mt][ft][u] = 0.f;
    float dnf[4] = {0.f, 0.f, 0.f, 0.f};

    for (int c = cstart; c < cend; c++) {
        int cur = c & 1;

        __half2 e01 = *(__half2*)&eu.x;
        __half2 e23 = *(__half2*)&eu.y;
        __half2 f01 = *(__half2*)&fu.x;
        __half2 f23 = *(__half2*)&fu.y;
#pragma unroll
        for (int q = 0; q < 4; q++) {
            uint4 a4 = av[q];
            __half2 w0 = __hmax2(__hmul2(aa[q], e01), __hmul2(bb[q], f01));
            unsigned m0 = a4.x * 0x3C00u + a4.y * 0x3C000000u;
            w0 = __hmul2(w0, *(__half2*)&m0);
            __half2 w1 = __hmax2(__hmul2(aa[q], e23), __hmul2(bb[q], f23));
            unsigned m1 = a4.z * 0x3C00u + a4.w * 0x3C000000u;
            w1 = __hmul2(w1, *(__half2*)&m1);
            __half2 dn2 = __hadd2(w0, w1);
            float2 df = __half22float2(dn2);
            dnf[q] += df.x + df.y;
            int rl = wid * 16 + 4 * q + rql;
            *(uint2*)&Ah_s[cur][rl * ASTR + 4 * jb] =
                make_uint2(*(unsigned*)&w0, *(unsigned*)&w1);
        }

        if (c + 1 < cend) {
#pragma unroll
            for (int q = 0; q < 4; q++) av[q] = adjp[q][(size_t)(c + 1) * 8];
            eu = epE[(c + 1) * 8 + jb];
            fu = epF[(c + 1) * 8 + jb];
        }

        CP_WAIT0();
        __syncthreads();

        if (c + 1 < cend) {
            cp16(&Bf_s[cur ^ 1][t * 8], &g_Bf[(c + 1) * 1024 + t * 8]);
            cp16(&Bf_s[cur ^ 1][t * 8 + 4], &g_Bf[(c + 1) * 1024 + t * 8 + 4]);
            CP_COMMIT();
        }

#pragma unroll
        for (int kt = 0; kt < 2; kt++) {
            uint2 bfr[4];
#pragma unroll
            for (int ft = 0; ft < 4; ft++) {
                int ftg = nw * 4 + ft;
                bfr[ft] = *(const uint2*)&Bf_s[cur][((kt * 8 + ftg) * 32 + lane) * 2];
            }
#pragma unroll
            for (int mt = 0; mt < 2; mt++) {
                unsigned addr = a_lane + (unsigned)(cur * (BM * ASTR * 2)) +
                    (unsigned)(((mw * 32 + mt * 16) * ASTR + kt * 16) * 2);
                unsigned a0, a1, a2, a3;
                asm("ldmatrix.sync.aligned.m8n8.x4.shared.b16 {%0,%1,%2,%3}, [%4];"
                    : "=r"(a0), "=r"(a1), "=r"(a2), "=r"(a3) : "r"(addr));
#pragma unroll
                for (int ft = 0; ft < 4; ft++)
                    mma_f16(acc[mt][ft], a0, a1, a2, a3, bfr[ft].x, bfr[ft].y);
            }
        }
    }

#pragma unroll
    for (int mt = 0; mt < 2; mt++) {
        int r1 = r0 + mw * 32 + mt * 16 + (lane >> 2);
#pragma unroll
        for (int ft = 0; ft < 4; ft++) {
            int col = nw * 32 + ft * 8 + (lane & 3) * 2;
            *(float2*)&g_num[bs][r1 * FF + col] = make_float2(acc[mt][ft][0], acc[mt][ft][1]);
            *(float2*)&g_num[bs][(r1 + 8) * FF + col] = make_float2(acc[mt][ft][2], acc[mt][ft][3]);
        }
    }
#pragma unroll
    for (int q = 0; q < 4; q++) {
        float v = dnf[q];
        v += __shfl_xor_sync(0xffffffffu, v, 1);
        v += __shfl_xor_sync(0xffffffffu, v, 2);
        v += __shfl_xor_sync(0xffffffffu, v, 4);
        if (jb == 0) g_den[bs][r0 + wid * 16 + 4 * q + rql] = v;
    }
}

// -------------------- K5: reduce splits, normalize, ELU --------------------
__global__ __launch_bounds__(256) void k5_out(float* __restrict__ out) {
    int idx4 = blockIdx.x * 256 + threadIdx.x;
    int idx = idx4 * 4;
    int i = idx >> 6;
    float4 num = make_float4(0.f, 0.f, 0.f, 0.f);
    float den = 0.f;
#pragma unroll
    for (int s = 0; s < SPLIT; s++) {
        float4 v = *(const float4*)&g_num[s][idx];
        num.x += v.x; num.y += v.y; num.z += v.z; num.w += v.w;
        den += g_den[s][i];
    }
    den = fmaxf(den, 1e-30f);
    float r = 1.f / den;
    float4 o;
    o.x = num.x * r; o.y = num.y * r; o.z = num.z * r; o.w = num.w * r;
    o.x = (o.x > 0.f) ? o.x : expm1f(o.x);
    o.y = (o.y > 0.f) ? o.y : expm1f(o.y);
    o.z = (o.z > 0.f) ? o.z : expm1f(o.z);
    o.w = (o.w > 0.f) ? o.w : expm1f(o.w);
    *(float4*)&out[idx] = o;
}

// -------------------- launch --------------------
extern "C" void kernel_launch(void* const* d_in, const int* in_sizes, int n_in,
                              void* d_out, int out_size) {
    const float* h = (const float*)d_in[0];
    const int* adj = (const int*)d_in[1];
    const float* W = (const float*)d_in[2];
    const float* a = (const float*)d_in[3];
    float* out = (float*)d_out;

    k0w<<<32, 256>>>(W);
    k1_gemm<<<NN / 64, 256>>>(h, a);
    k3_ef<<<NN / 256, 256>>>();
    k4_main<<<128 * SPLIT, 128>>>(adj);
    k5_out<<<(NN * FF) / 1024, 256>>>(out);
}